// round 7
// baseline (speedup 1.0000x reference)
#include <cuda_runtime.h>

#define BATCH 8
#define CH    64
#define HH    256
#define WW    256
#define TW    16
#define NT    16                 // tiles along W
#define NCTA  (BATCH * NT)       // 128 CTAs, one wave
#define NTHR  512                // 64 co x 8 ci-groups
#define CIPT  8                  // ci per thread
#define NCIG  8
#define PSTR  18                 // pp row stride in u64 (144 B, 16B-aligned)

typedef unsigned long long u64;

union F4U { float4 f; u64 u[2]; };

__device__ int   g_progress[NCTA];
__device__ float g_halo[2][NCTA][2][CH];   // [row parity][cta][left/right edge][ch]

// ---- packed f32x2 ops ------------------------------------------------------
static __device__ __forceinline__ u64 fma2(u64 a, u64 b, u64 c) {
    u64 d; asm("fma.rn.f32x2 %0, %1, %2, %3;" : "=l"(d) : "l"(a), "l"(b), "l"(c)); return d;
}
static __device__ __forceinline__ u64 add2(u64 a, u64 b) {
    u64 d; asm("add.rn.f32x2 %0, %1, %2;" : "=l"(d) : "l"(a), "l"(b)); return d;
}
static __device__ __forceinline__ u64 splat2(float x) {
    u64 r; asm("mov.b64 %0, {%1, %1};" : "=l"(r) : "f"(x)); return r;
}
static __device__ __forceinline__ u64 pack2(float lo, float hi) {
    u64 r; asm("mov.b64 %0, {%1, %2};" : "=l"(r) : "f"(lo), "f"(hi)); return r;
}
static __device__ __forceinline__ void unpack2(u64 v, float& lo, float& hi) {
    unsigned a, b;
    asm("mov.b64 {%0,%1}, %2;" : "=r"(a), "=r"(b) : "l"(v));
    lo = __uint_as_float(a); hi = __uint_as_float(b);
}
static __device__ __forceinline__ float ftanh(float x) {
    float e = __expf(2.0f * x);
    return 1.0f - __fdividef(2.0f, e + 1.0f);
}

// ---- release/acquire flag ops ----------------------------------------------
static __device__ __forceinline__ int ld_acq(const int* p) {
    int v;
    asm volatile("ld.acquire.gpu.global.b32 %0, [%1];" : "=r"(v) : "l"(p));
    return v;
}
static __device__ __forceinline__ void st_rel(int* p, int v) {
    asm volatile("st.release.gpu.global.b32 [%0], %1;" :: "l"(p), "r"(v) : "memory");
}

__global__ void reset_kernel() {
    if (threadIdx.x < NCTA) g_progress[threadIdx.x] = -1;
}

__global__ void __launch_bounds__(NTHR, 1)
spatial_kernel(const float* __restrict__ X, const float* __restrict__ Wc,
               const float* __restrict__ bc, float* __restrict__ out) {
    __shared__ u64 pp[2][CH][PSTR];          // pair rows (v[j-1],v[j]), dbl buf 18 KB
    __shared__ u64 red[NCIG][NCIG][CH];      // partials [cig][pair][co]       32 KB

    const int tid = threadIdx.x;
    const int co  = tid & 63;            // channel
    const int cig = tid >> 6;            // ci-group == w-pair in epilogue
    const int bid = blockIdx.x;
    const int b   = bid >> 4;
    const int t   = bid & 15;            // tile position along W
    const int w0  = t * TW;
    const int o0  = cig * 2;             // this thread's two output columns

    // ---- weights: 8 ci x 3 taps into registers ----
    float wr[CIPT * 3];
    {
        const float4* wp = reinterpret_cast<const float4*>(
            Wc + ((size_t)co * CH + cig * CIPT) * 3);
#pragma unroll
        for (int i = 0; i < 6; i++) {
            float4 v = wp[i];
            wr[i * 4 + 0] = v.x; wr[i * 4 + 1] = v.y;
            wr[i * 4 + 2] = v.z; wr[i * 4 + 3] = v.w;
        }
    }
    const float bias = bc[co];

    // permanent zero halo slots: q[0].lo and q[16].hi never written elsewhere
    if (tid < CH) {
        reinterpret_cast<float2*>(&pp[0][tid][0])->x  = 0.f;
        reinterpret_cast<float2*>(&pp[1][tid][0])->x  = 0.f;
        reinterpret_cast<float2*>(&pp[0][tid][16])->y = 0.f;
        reinterpret_cast<float2*>(&pp[1][tid][16])->y = 0.f;
    }

    // ---- row 0: Y[0] = X[0] ----
    const size_t chb = ((size_t)(b * CH + co) * HH) * WW + w0;
    {
        float2 x2 = *reinterpret_cast<const float2*>(X + chb + o0);
        *reinterpret_cast<float2*>(out + chb + o0) = x2;
        float2* pr = reinterpret_cast<float2*>(&pp[0][co][0]);
        pr[o0].y = x2.x; pr[o0 + 1].x = x2.x;
        pr[o0 + 1].y = x2.y; pr[o0 + 2].x = x2.y;
        if (cig == 0)        g_halo[0][bid][0][co] = x2.x;   // w = 0
        if (cig == NCIG - 1) g_halo[0][bid][1][co] = x2.y;   // w = 15
    }
    __syncthreads();
    if (tid == 0) st_rel(&g_progress[bid], 0);

    int cur = 0;
    for (int h = 1; h < HH; h++) {
        const size_t rb = chb + (size_t)h * WW;
        float2 x2 = *reinterpret_cast<const float2*>(X + rb + o0);   // early LDG

        // ---- conv: 8 ci rows x all 16 w (8 packed accumulators) ----
        u64 s[8];
#pragma unroll
        for (int p = 0; p < 8; p++) s[p] = 0ull;
        const u64* rowbase = &pp[cur][cig * CIPT][0];
#pragma unroll
        for (int j = 0; j < CIPT; j++) {
            const u64* q = rowbase + j * PSTR;
            const float4* q4 = reinterpret_cast<const float4*>(q);
            F4U r0, r1, r2, r3, r4, r5, r6, r7;
            r0.f = q4[0]; r1.f = q4[1]; r2.f = q4[2]; r3.f = q4[3];
            r4.f = q4[4]; r5.f = q4[5]; r6.f = q4[6]; r7.f = q4[7];
            u64 q16 = q[16];
            u64 k0 = splat2(wr[j * 3 + 0]);
            u64 k1 = splat2(wr[j * 3 + 1]);
            u64 k2 = splat2(wr[j * 3 + 2]);
            s[0] = fma2(k0, r0.u[0], s[0]); s[0] = fma2(k1, r0.u[1], s[0]); s[0] = fma2(k2, r1.u[0], s[0]);
            s[1] = fma2(k0, r1.u[0], s[1]); s[1] = fma2(k1, r1.u[1], s[1]); s[1] = fma2(k2, r2.u[0], s[1]);
            s[2] = fma2(k0, r2.u[0], s[2]); s[2] = fma2(k1, r2.u[1], s[2]); s[2] = fma2(k2, r3.u[0], s[2]);
            s[3] = fma2(k0, r3.u[0], s[3]); s[3] = fma2(k1, r3.u[1], s[3]); s[3] = fma2(k2, r4.u[0], s[3]);
            s[4] = fma2(k0, r4.u[0], s[4]); s[4] = fma2(k1, r4.u[1], s[4]); s[4] = fma2(k2, r5.u[0], s[4]);
            s[5] = fma2(k0, r5.u[0], s[5]); s[5] = fma2(k1, r5.u[1], s[5]); s[5] = fma2(k2, r6.u[0], s[5]);
            s[6] = fma2(k0, r6.u[0], s[6]); s[6] = fma2(k1, r6.u[1], s[6]); s[6] = fma2(k2, r7.u[0], s[6]);
            s[7] = fma2(k0, r7.u[0], s[7]); s[7] = fma2(k1, r7.u[1], s[7]); s[7] = fma2(k2, q16,     s[7]);
        }

        // ---- wait for neighbors' row h-1 (combined poll, then both halo LDGs) ----
        const int par  = (h - 1) & 1;
        const int need = h - 1;
        if (t > 0 || t < NT - 1) {
            for (;;) {
                int fL = (t > 0)      ? ld_acq(&g_progress[bid - 1]) : need;
                int fR = (t < NT - 1) ? ld_acq(&g_progress[bid + 1]) : need;
                if (fL >= need && fR >= need) break;
            }
        }
        float4 mL0 = make_float4(0.f,0.f,0.f,0.f), mL1 = mL0;
        float4 mR0 = mL0, mR1 = mL0;
        if (t > 0) {
            const float4* p4 = reinterpret_cast<const float4*>(&g_halo[par][bid - 1][1][cig * CIPT]);
            mL0 = __ldcg(p4); mL1 = __ldcg(p4 + 1);
        }
        if (t < NT - 1) {
            const float4* p4 = reinterpret_cast<const float4*>(&g_halo[par][bid + 1][0][cig * CIPT]);
            mR0 = __ldcg(p4); mR1 = __ldcg(p4 + 1);
        }

        // ---- halo corrections over this thread's 8 ci ----
        {
            float cL = wr[0]  * mL0.x + wr[3]  * mL0.y + wr[6]  * mL0.z + wr[9]  * mL0.w
                     + wr[12] * mL1.x + wr[15] * mL1.y + wr[18] * mL1.z + wr[21] * mL1.w;
            float cR = wr[2]  * mR0.x + wr[5]  * mR0.y + wr[8]  * mR0.z + wr[11] * mR0.w
                     + wr[14] * mR1.x + wr[17] * mR1.y + wr[20] * mR1.z + wr[23] * mR1.w;
            float lo, hi;
            unpack2(s[0], lo, hi); s[0] = pack2(lo + cL, hi);
            unpack2(s[7], lo, hi); s[7] = pack2(lo, hi + cR);
        }

        // ---- cross-group reduction ----
#pragma unroll
        for (int p = 0; p < 8; p++) red[cig][p][co] = s[p];
        __syncthreads();   // S1

        u64 acc = red[0][cig][co];
#pragma unroll
        for (int c = 1; c < NCIG; c++) acc = add2(acc, red[c][cig][co]);
        float slo, shi;
        unpack2(acc, slo, shi);
        float y0 = x2.x + ftanh(slo + bias);
        float y1 = x2.y + ftanh(shi + bias);

        *reinterpret_cast<float2*>(out + rb + o0) = make_float2(y0, y1);

        const int nxt = cur ^ 1;
        float2* pr = reinterpret_cast<float2*>(&pp[nxt][co][0]);
        pr[o0].y = y0; pr[o0 + 1].x = y0;
        pr[o0 + 1].y = y1; pr[o0 + 2].x = y1;

        if (cig == 0)        g_halo[h & 1][bid][0][co] = y0;  // w = 0
        if (cig == NCIG - 1) g_halo[h & 1][bid][1][co] = y1;  // w = 15

        __syncthreads();   // S2: pp[nxt] + halo stores done, red reads done
        if (tid == 0) st_rel(&g_progress[bid], h);
        cur = nxt;
    }
}

extern "C" void kernel_launch(void* const* d_in, const int* in_sizes, int n_in,
                              void* d_out, int out_size) {
    const float* X  = (const float*)d_in[0];
    const float* Wc = (const float*)d_in[1];
    const float* bc = (const float*)d_in[2];
    float* out = (float*)d_out;

    reset_kernel<<<1, NCTA>>>();
    spatial_kernel<<<NCTA, NTHR>>>(X, Wc, bc, out);
}

// round 10
// speedup vs baseline: 2.4662x; 2.4662x over previous
#include <cuda_runtime.h>

#define BATCH 8
#define CH    64
#define HH    256
#define WW    256
#define TW    16
#define NT    16                 // tiles along W
#define NCTA  (BATCH * NT)       // 128 CTAs, one wave
#define NTHR  512                // 64 co x 8 ci-groups
#define CIPT  8                  // ci per thread
#define NCIG  8
#define PSTR  18                 // pp row stride in u64 (144 B, 16B-aligned)

typedef unsigned long long u64;

union F4U { float4 f; u64 u[2]; };

__device__ int   g_progress[NCTA];
__device__ float g_halo[2][NCTA][2][CH];   // [row parity][cta][left/right edge][ch]

// ---- packed f32x2 ops ------------------------------------------------------
static __device__ __forceinline__ u64 fma2(u64 a, u64 b, u64 c) {
    u64 d; asm("fma.rn.f32x2 %0, %1, %2, %3;" : "=l"(d) : "l"(a), "l"(b), "l"(c)); return d;
}
static __device__ __forceinline__ u64 add2(u64 a, u64 b) {
    u64 d; asm("add.rn.f32x2 %0, %1, %2;" : "=l"(d) : "l"(a), "l"(b)); return d;
}
static __device__ __forceinline__ u64 splat2(float x) {
    u64 r; asm("mov.b64 %0, {%1, %1};" : "=l"(r) : "f"(x)); return r;
}
static __device__ __forceinline__ u64 pack2(float lo, float hi) {
    u64 r; asm("mov.b64 %0, {%1, %2};" : "=l"(r) : "f"(lo), "f"(hi)); return r;
}
static __device__ __forceinline__ void unpack2(u64 v, float& lo, float& hi) {
    unsigned a, b;
    asm("mov.b64 {%0,%1}, %2;" : "=r"(a), "=r"(b) : "l"(v));
    lo = __uint_as_float(a); hi = __uint_as_float(b);
}
static __device__ __forceinline__ float ftanh(float x) {
    float e = __expf(2.0f * x);
    return 1.0f - __fdividef(2.0f, e + 1.0f);
}

// ---- release/acquire flag ops ----------------------------------------------
static __device__ __forceinline__ int ld_acq(const int* p) {
    int v;
    asm volatile("ld.acquire.gpu.global.b32 %0, [%1];" : "=r"(v) : "l"(p));
    return v;
}
static __device__ __forceinline__ void st_rel(int* p, int v) {
    asm volatile("st.release.gpu.global.b32 [%0], %1;" :: "l"(p), "r"(v) : "memory");
}

__global__ void reset_kernel() {
    if (threadIdx.x < NCTA) g_progress[threadIdx.x] = -1;
}

__global__ void __launch_bounds__(NTHR, 1)
spatial_kernel(const float* __restrict__ X, const float* __restrict__ Wc,
               const float* __restrict__ bc, float* __restrict__ out) {
    __shared__ u64 pp[2][CH][PSTR];          // pair rows (v[j-1],v[j]), dbl buf 18 KB
    __shared__ u64 red[NCIG][NCIG][CH];      // partials [cig][pair][co]       32 KB

    const int tid = threadIdx.x;
    const int co  = tid & 63;            // channel
    const int cig = tid >> 6;            // ci-group == w-pair in epilogue
    const int bid = blockIdx.x;
    const int b   = bid >> 4;
    const int t   = bid & 15;            // tile position along W
    const int w0  = t * TW;
    const int o0  = cig * 2;             // this thread's two output columns

    // ---- weights: 8 ci x 3 taps into registers ----
    float wr[CIPT * 3];
    {
        const float4* wp = reinterpret_cast<const float4*>(
            Wc + ((size_t)co * CH + cig * CIPT) * 3);
#pragma unroll
        for (int i = 0; i < 6; i++) {
            float4 v = wp[i];
            wr[i * 4 + 0] = v.x; wr[i * 4 + 1] = v.y;
            wr[i * 4 + 2] = v.z; wr[i * 4 + 3] = v.w;
        }
    }
    const float bias = bc[co];

    // permanent zero halo slots: q[0].lo and q[16].hi never written elsewhere
    if (tid < CH) {
        reinterpret_cast<float2*>(&pp[0][tid][0])->x  = 0.f;
        reinterpret_cast<float2*>(&pp[1][tid][0])->x  = 0.f;
        reinterpret_cast<float2*>(&pp[0][tid][16])->y = 0.f;
        reinterpret_cast<float2*>(&pp[1][tid][16])->y = 0.f;
    }

    // ---- row 0: Y[0] = X[0] ----
    const size_t chb = ((size_t)(b * CH + co) * HH) * WW + w0;
    {
        float2 x2 = *reinterpret_cast<const float2*>(X + chb + o0);
        *reinterpret_cast<float2*>(out + chb + o0) = x2;
        float2* pr = reinterpret_cast<float2*>(&pp[0][co][0]);
        pr[o0].y = x2.x; pr[o0 + 1].x = x2.x;
        pr[o0 + 1].y = x2.y; pr[o0 + 2].x = x2.y;
        if (cig == 0)        g_halo[0][bid][0][co] = x2.x;   // w = 0
        if (cig == NCIG - 1) g_halo[0][bid][1][co] = x2.y;   // w = 15
    }
    __syncthreads();
    if (tid == 0) st_rel(&g_progress[bid], 0);

    int cur = 0;
    for (int h = 1; h < HH; h++) {
        const int par  = (h - 1) & 1;
        const int need = h - 1;

        // ---- spin: exactly two pollster threads (R4 pattern) ----
        if (tid == 0 && t > 0)
            while (ld_acq(&g_progress[bid - 1]) < need) { }
        if (tid == 256 && t < NT - 1)
            while (ld_acq(&g_progress[bid + 1]) < need) { }
        __syncthreads();   // S1: neighbor data for row h-1 is published

        // ---- issue all long-latency loads; consumed after the conv ----
        float4 mL0 = make_float4(0.f,0.f,0.f,0.f), mL1 = mL0;
        float4 mR0 = mL0, mR1 = mL0;
        if (t > 0) {
            const float4* p4 = reinterpret_cast<const float4*>(&g_halo[par][bid - 1][1][cig * CIPT]);
            mL0 = __ldcg(p4); mL1 = __ldcg(p4 + 1);
        }
        if (t < NT - 1) {
            const float4* p4 = reinterpret_cast<const float4*>(&g_halo[par][bid + 1][0][cig * CIPT]);
            mR0 = __ldcg(p4); mR1 = __ldcg(p4 + 1);
        }
        const size_t rb = chb + (size_t)h * WW;
        float2 x2 = *reinterpret_cast<const float2*>(X + rb + o0);

        // ---- conv: 8 ci rows x all 16 w (8 packed accumulators) ----
        u64 s[8];
#pragma unroll
        for (int p = 0; p < 8; p++) s[p] = 0ull;
        const u64* rowbase = &pp[cur][cig * CIPT][0];
#pragma unroll
        for (int j = 0; j < CIPT; j++) {
            const u64* q = rowbase + j * PSTR;
            const float4* q4 = reinterpret_cast<const float4*>(q);
            F4U r0, r1, r2, r3, r4, r5, r6, r7;
            r0.f = q4[0]; r1.f = q4[1]; r2.f = q4[2]; r3.f = q4[3];
            r4.f = q4[4]; r5.f = q4[5]; r6.f = q4[6]; r7.f = q4[7];
            u64 q16 = q[16];
            u64 k0 = splat2(wr[j * 3 + 0]);
            u64 k1 = splat2(wr[j * 3 + 1]);
            u64 k2 = splat2(wr[j * 3 + 2]);
            s[0] = fma2(k0, r0.u[0], s[0]); s[0] = fma2(k1, r0.u[1], s[0]); s[0] = fma2(k2, r1.u[0], s[0]);
            s[1] = fma2(k0, r1.u[0], s[1]); s[1] = fma2(k1, r1.u[1], s[1]); s[1] = fma2(k2, r2.u[0], s[1]);
            s[2] = fma2(k0, r2.u[0], s[2]); s[2] = fma2(k1, r2.u[1], s[2]); s[2] = fma2(k2, r3.u[0], s[2]);
            s[3] = fma2(k0, r3.u[0], s[3]); s[3] = fma2(k1, r3.u[1], s[3]); s[3] = fma2(k2, r4.u[0], s[3]);
            s[4] = fma2(k0, r4.u[0], s[4]); s[4] = fma2(k1, r4.u[1], s[4]); s[4] = fma2(k2, r5.u[0], s[4]);
            s[5] = fma2(k0, r5.u[0], s[5]); s[5] = fma2(k1, r5.u[1], s[5]); s[5] = fma2(k2, r6.u[0], s[5]);
            s[6] = fma2(k0, r6.u[0], s[6]); s[6] = fma2(k1, r6.u[1], s[6]); s[6] = fma2(k2, r7.u[0], s[6]);
            s[7] = fma2(k0, r7.u[0], s[7]); s[7] = fma2(k1, r7.u[1], s[7]); s[7] = fma2(k2, q16,     s[7]);
        }

        // ---- halo corrections over this thread's 8 ci ----
        {
            float cL = wr[0]  * mL0.x + wr[3]  * mL0.y + wr[6]  * mL0.z + wr[9]  * mL0.w
                     + wr[12] * mL1.x + wr[15] * mL1.y + wr[18] * mL1.z + wr[21] * mL1.w;
            float cR = wr[2]  * mR0.x + wr[5]  * mR0.y + wr[8]  * mR0.z + wr[11] * mR0.w
                     + wr[14] * mR1.x + wr[17] * mR1.y + wr[20] * mR1.z + wr[23] * mR1.w;
            float lo, hi;
            unpack2(s[0], lo, hi); s[0] = pack2(lo + cL, hi);
            unpack2(s[7], lo, hi); s[7] = pack2(lo, hi + cR);
        }

        // ---- cross-group reduction ----
#pragma unroll
        for (int p = 0; p < 8; p++) red[cig][p][co] = s[p];
        __syncthreads();   // S2

        u64 acc = red[0][cig][co];
#pragma unroll
        for (int c = 1; c < NCIG; c++) acc = add2(acc, red[c][cig][co]);
        float slo, shi;
        unpack2(acc, slo, shi);
        float y0 = x2.x + ftanh(slo + bias);
        float y1 = x2.y + ftanh(shi + bias);

        *reinterpret_cast<float2*>(out + rb + o0) = make_float2(y0, y1);

        const int nxt = cur ^ 1;
        float2* pr = reinterpret_cast<float2*>(&pp[nxt][co][0]);
        pr[o0].y = y0; pr[o0 + 1].x = y0;
        pr[o0 + 1].y = y1; pr[o0 + 2].x = y1;

        if (cig == 0)        g_halo[h & 1][bid][0][co] = y0;  // w = 0
        if (cig == NCIG - 1) g_halo[h & 1][bid][1][co] = y1;  // w = 15

        __syncthreads();   // S3: pp[nxt] + halo stores done, red reads done
        if (tid == 0) st_rel(&g_progress[bid], h);
        cur = nxt;
    }
}

extern "C" void kernel_launch(void* const* d_in, const int* in_sizes, int n_in,
                              void* d_out, int out_size) {
    const float* X  = (const float*)d_in[0];
    const float* Wc = (const float*)d_in[1];
    const float* bc = (const float*)d_in[2];
    float* out = (float*)d_out;

    reset_kernel<<<1, NCTA>>>();
    spatial_kernel<<<NCTA, NTHR>>>(X, Wc, bc, out);
}